// round 10
// baseline (speedup 1.0000x reference)
#include <cuda_runtime.h>
#include <cuda_fp16.h>
#include <math.h>
#include <stdint.h>
#include <mma.h>

using namespace nvcuda;

#define NMAX   50000
#define NPAD   50048               // ceil(50000/128)*128 for unmasked wmma stores
#define EMAX   800000
#define K1     512
#define F1     256
#define F2     64
#define SCANB  256

// ---------------- scratch (static device globals) --------------------------
__device__ int    g_deg_out[NMAX];
__device__ int    g_deg_in [NMAX];
__device__ int    g_cursor [NMAX];
__device__ int    g_row_start[NMAX + 1];
__device__ int    g_part[SCANB];
__device__ int    g_esrc[EMAX];
__device__ float  g_ew  [EMAX];             // nsrc[src[e]] per bucketed edge
__device__ float  g_nsrc[NMAX];
__device__ float  g_ndst[NMAX];
__device__ __half g_H1h[(size_t)NPAD * F1]; // GEMM1 out, fp16 (gathered by agg1)
__device__ float  g_A1[(size_t)NMAX * F1];  // agg1 out, fp32 (GEMM2 input)
__device__ __half g_H2h[(size_t)NMAX * F2]; // GEMM2 out, fp16 (gathered by agg2)

// ---------------- fused init ------------------------------------------------
__global__ void k_init(int n) {
    int i = blockIdx.x * blockDim.x + threadIdx.x;
    if (i < n) { g_deg_out[i] = 0; g_deg_in[i] = 0; g_cursor[i] = 0; }
}

// ---------------- degrees / norms ------------------------------------------
__global__ void k_deg(const int* __restrict__ src, const int* __restrict__ dst, int E) {
    int e = blockIdx.x * blockDim.x + threadIdx.x;
    if (e < E) {
        atomicAdd(&g_deg_out[src[e]], 1);
        atomicAdd(&g_deg_in [dst[e]], 1);
    }
}

__global__ void k_norm(int n) {
    int i = blockIdx.x * blockDim.x + threadIdx.x;
    if (i < n) {
        int o = g_deg_out[i], d = g_deg_in[i];
        g_nsrc[i] = (o > 0) ? rsqrtf((float)o) : 1.0f;
        g_ndst[i] = (d > 0) ? rsqrtf((float)d) : 1.0f;
    }
}

// ---------------- 3-phase multi-block scan: deg_in -> row_start -------------
__device__ __forceinline__ int warp_incl_scan(int v) {
#pragma unroll
    for (int off = 1; off < 32; off <<= 1) {
        int t = __shfl_up_sync(0xFFFFFFFFu, v, off);
        if ((threadIdx.x & 31) >= off) v += t;
    }
    return v;
}

__global__ void k_scan1(int n) {
    int i = blockIdx.x * SCANB + threadIdx.x;
    int v = (i < n) ? g_deg_in[i] : 0;
    int s = v;
#pragma unroll
    for (int off = 16; off > 0; off >>= 1) s += __shfl_down_sync(0xFFFFFFFFu, s, off);
    __shared__ int ws[SCANB / 32];
    if ((threadIdx.x & 31) == 0) ws[threadIdx.x >> 5] = s;
    __syncthreads();
    if (threadIdx.x == 0) {
        int t = 0;
#pragma unroll
        for (int w = 0; w < SCANB / 32; w++) t += ws[w];
        g_part[blockIdx.x] = t;
    }
}

__global__ void k_scan2(int nb) {
    int v = (threadIdx.x < nb) ? g_part[threadIdx.x] : 0;
    int s = warp_incl_scan(v);
    __shared__ int ws[SCANB / 32];
    if ((threadIdx.x & 31) == 31) ws[threadIdx.x >> 5] = s;
    __syncthreads();
    if (threadIdx.x < 32) {
        int w = (threadIdx.x < SCANB / 32) ? ws[threadIdx.x] : 0;
        int sw = warp_incl_scan(w);
        if (threadIdx.x < SCANB / 32) ws[threadIdx.x] = sw;
    }
    __syncthreads();
    int incl = s + ((threadIdx.x >= 32) ? ws[(threadIdx.x >> 5) - 1] : 0);
    if (threadIdx.x < nb) g_part[threadIdx.x] = incl - v;
}

__global__ void k_scan3(int n) {
    int i = blockIdx.x * SCANB + threadIdx.x;
    int v = (i < n) ? g_deg_in[i] : 0;
    int s = warp_incl_scan(v);
    __shared__ int ws[SCANB / 32];
    if ((threadIdx.x & 31) == 31) ws[threadIdx.x >> 5] = s;
    __syncthreads();
    if (threadIdx.x < 32) {
        int w = (threadIdx.x < SCANB / 32) ? ws[threadIdx.x] : 0;
        int sw = warp_incl_scan(w);
        if (threadIdx.x < SCANB / 32) ws[threadIdx.x] = sw;
    }
    __syncthreads();
    int incl = s + ((threadIdx.x >= 32) ? ws[(threadIdx.x >> 5) - 1] : 0);
    int off = g_part[blockIdx.x];
    if (i < n) g_row_start[i] = off + incl - v;
    if (i == n - 1) g_row_start[n] = off + incl;
}

// ---------------- bucket edges by dst --------------------------------------
__global__ void k_fill(const int* __restrict__ src, const int* __restrict__ dst, int E) {
    int e = blockIdx.x * blockDim.x + threadIdx.x;
    if (e < E) {
        int s = src[e];
        int d = dst[e];
        int pos = g_row_start[d] + atomicAdd(&g_cursor[d], 1);
        g_esrc[pos] = s;
        g_ew [pos] = g_nsrc[s];
    }
}

// ---------------- TF32 wmma GEMM1:  Ch = half(A @ B), rows padded ----------
__global__ void __launch_bounds__(256) gemm_wmma_h(
    const float* __restrict__ A, const float* __restrict__ B,
    __half* __restrict__ Ch, int M, int K, int N) {
    constexpr int BM = 128, BN = 128, BK = 16;
    constexpr int AST = BK + 4;
    constexpr int BST = BN + 4;
    __shared__ float As[2][BM * AST];
    __shared__ float Bs[2][BK * BST];

    const int tid  = threadIdx.x;
    const int wid  = tid >> 5;
    const int lane = tid & 31;
    const int wm   = (wid & 1) * 64;
    const int wn   = (wid >> 1) * 32;
    const int bm   = blockIdx.x * BM;
    const int bn   = blockIdx.y * BN;

    wmma::fragment<wmma::accumulator, 16, 16, 8, float> fc[4][2];
#pragma unroll
    for (int i = 0; i < 4; i++)
#pragma unroll
        for (int j = 0; j < 2; j++) wmma::fill_fragment(fc[i][j], 0.0f);

    float4 ra[2], rb[2];

    auto loadA = [&](int k0) {
#pragma unroll
        for (int u = 0; u < 2; u++) {
            int idx = tid + u * 256;
            int m   = idx >> 2;
            int kq  = idx & 3;
            int gm  = bm + m;
            float4 v = make_float4(0.f, 0.f, 0.f, 0.f);
            if (gm < M) v = *(const float4*)(A + (size_t)gm * K + k0 + kq * 4);
            ra[u] = v;
        }
    };
    auto loadB = [&](int k0) {
#pragma unroll
        for (int u = 0; u < 2; u++) {
            int idx = tid + u * 256;
            int k   = idx >> 5;
            int n4  = idx & 31;
            rb[u] = *(const float4*)(B + (size_t)(k0 + k) * N + bn + n4 * 4);
        }
    };
    auto stage = [&](int st) {
#pragma unroll
        for (int u = 0; u < 2; u++) {
            int idx = tid + u * 256;
            int m = idx >> 2, kq = idx & 3;
            float* p = &As[st][m * AST + kq * 4];
            p[0] = wmma::__float_to_tf32(ra[u].x);
            p[1] = wmma::__float_to_tf32(ra[u].y);
            p[2] = wmma::__float_to_tf32(ra[u].z);
            p[3] = wmma::__float_to_tf32(ra[u].w);
        }
#pragma unroll
        for (int u = 0; u < 2; u++) {
            int idx = tid + u * 256;
            int k = idx >> 5, n4 = idx & 31;
            float* p = &Bs[st][k * BST + n4 * 4];
            p[0] = wmma::__float_to_tf32(rb[u].x);
            p[1] = wmma::__float_to_tf32(rb[u].y);
            p[2] = wmma::__float_to_tf32(rb[u].z);
            p[3] = wmma::__float_to_tf32(rb[u].w);
        }
    };

    loadA(0); loadB(0);
    stage(0);
    __syncthreads();

    const int nt = K / BK;
    for (int t = 0; t < nt; t++) {
        int st = t & 1;
        if (t + 1 < nt) { loadA((t + 1) * BK); loadB((t + 1) * BK); }

#pragma unroll
        for (int ks = 0; ks < BK; ks += 8) {
            wmma::fragment<wmma::matrix_a, 16, 16, 8, wmma::precision::tf32, wmma::row_major> fa[4];
            wmma::fragment<wmma::matrix_b, 16, 16, 8, wmma::precision::tf32, wmma::row_major> fb[2];
#pragma unroll
            for (int i = 0; i < 4; i++)
                wmma::load_matrix_sync(fa[i], &As[st][(wm + i * 16) * AST + ks], AST);
#pragma unroll
            for (int j = 0; j < 2; j++)
                wmma::load_matrix_sync(fb[j], &Bs[st][ks * BST + wn + j * 16], BST);
#pragma unroll
            for (int i = 0; i < 4; i++)
#pragma unroll
                for (int j = 0; j < 2; j++)
                    wmma::mma_sync(fc[i][j], fa[i], fb[j], fc[i][j]);
        }

        if (t + 1 < nt) { stage(st ^ 1); }
        __syncthreads();
    }

    // epilogue: per-warp smem staging, convert to half, 16B stores.
    __syncthreads();
    float* epi = ((float*)As) + wid * 256;    // 256 floats per warp (8 KB total)
    const int r  = lane >> 1;
    const int c8 = (lane & 1) * 8;
#pragma unroll
    for (int i = 0; i < 4; i++) {
#pragma unroll
        for (int j = 0; j < 2; j++) {
            wmma::store_matrix_sync(epi, fc[i][j], 16, wmma::mem_row_major);
            __syncwarp();
            const float* p = epi + r * 16 + c8;
            __half2 h0 = __floats2half2_rn(p[0], p[1]);
            __half2 h1 = __floats2half2_rn(p[2], p[3]);
            __half2 h2 = __floats2half2_rn(p[4], p[5]);
            __half2 h3 = __floats2half2_rn(p[6], p[7]);
            uint4 q;
            q.x = *(uint32_t*)&h0; q.y = *(uint32_t*)&h1;
            q.z = *(uint32_t*)&h2; q.w = *(uint32_t*)&h3;
            int grow = bm + wm + i * 16 + r;
            int gcol = bn + wn + j * 16 + c8;
            *(uint4*)(Ch + (size_t)grow * N + gcol) = q;   // rows < NPAD always
            __syncwarp();
        }
    }
}

// ---------------- fp32 SIMT SGEMM -> half out (GEMM2) ----------------------
template<int BM, int BN, int BK, int TM, int TN>
__global__ void sgemm_h(const float* __restrict__ A, const float* __restrict__ B,
                        __half* __restrict__ C, int M, int K, int N) {
    constexpr int NT  = (BM / TM) * (BN / TN);
    constexpr int ASS = BM + 4;
    __shared__ float As[BK][ASS];
    __shared__ float Bs[BK][BN];

    const int tid  = threadIdx.x;
    const int bm   = blockIdx.x * BM;
    const int bn   = blockIdx.y * BN;
    const int tcol = tid % (BN / TN);
    const int trow = tid / (BN / TN);

    float acc[TM][TN];
#pragma unroll
    for (int i = 0; i < TM; i++)
#pragma unroll
        for (int j = 0; j < TN; j++) acc[i][j] = 0.0f;

    constexpr int AF4 = BM * BK / 4;
    constexpr int BF4 = BK * BN / 4;

    for (int k0 = 0; k0 < K; k0 += BK) {
#pragma unroll
        for (int idx = tid; idx < AF4; idx += NT) {
            int m  = idx / (BK / 4);
            int kk = (idx % (BK / 4)) * 4;
            int gm = bm + m;
            float4 v = make_float4(0.f, 0.f, 0.f, 0.f);
            if (gm < M) v = *(const float4*)(A + (size_t)gm * K + k0 + kk);
            As[kk + 0][m] = v.x; As[kk + 1][m] = v.y;
            As[kk + 2][m] = v.z; As[kk + 3][m] = v.w;
        }
#pragma unroll
        for (int idx = tid; idx < BF4; idx += NT) {
            int k  = idx / (BN / 4);
            int n4 = idx % (BN / 4);
            *(float4*)&Bs[k][n4 * 4] =
                *(const float4*)(B + (size_t)(k0 + k) * N + bn + n4 * 4);
        }
        __syncthreads();

#pragma unroll
        for (int k = 0; k < BK; k++) {
            float ra[TM], rb[TN];
#pragma unroll
            for (int i = 0; i < TM; i += 4) {
                float4 t = *(const float4*)&As[k][trow * TM + i];
                ra[i] = t.x; ra[i + 1] = t.y; ra[i + 2] = t.z; ra[i + 3] = t.w;
            }
#pragma unroll
            for (int j = 0; j < TN; j += 4) {
                float4 t = *(const float4*)&Bs[k][tcol * TN + j];
                rb[j] = t.x; rb[j + 1] = t.y; rb[j + 2] = t.z; rb[j + 3] = t.w;
            }
#pragma unroll
            for (int i = 0; i < TM; i++)
#pragma unroll
                for (int j = 0; j < TN; j++)
                    acc[i][j] = fmaf(ra[i], rb[j], acc[i][j]);
        }
        __syncthreads();
    }

#pragma unroll
    for (int i = 0; i < TM; i++) {
        int gm = bm + trow * TM + i;
        if (gm < M) {
            static_assert(TN == 4, "epilogue packs 4 cols");
            __half2 h0 = __floats2half2_rn(acc[i][0], acc[i][1]);
            __half2 h1 = __floats2half2_rn(acc[i][2], acc[i][3]);
            uint2 q;
            q.x = *(uint32_t*)&h0; q.y = *(uint32_t*)&h1;
            *(uint2*)(C + (size_t)gm * N + bn + tcol * TN) = q;
        }
    }
}

// ---------------- agg1 (F=256, fp16 gather): one warp/node -----------------
// Row = 32 uint4 (8 halves each); lane l owns features l*8..l*8+7.
__global__ void k_agg256h(const __half* __restrict__ H, const float* __restrict__ bias,
                          float* __restrict__ out, int N) {
    int node = blockIdx.x * 8 + (threadIdx.x >> 5);
    int lane = threadIdx.x & 31;
    if (node >= N) return;

    int beg = g_row_start[node];
    int end = g_row_start[node + 1];

    const uint4* Hv = (const uint4*)H;           // 32 uint4 per row
    float a0[8], a1[8];
#pragma unroll
    for (int k = 0; k < 8; k++) { a0[k] = 0.f; a1[k] = 0.f; }

    auto acc8 = [](float* a, uint4 q, float w) {
        __half2* h = (__half2*)&q;
#pragma unroll
        for (int k = 0; k < 4; k++) {
            float2 f = __half22float2(h[k]);
            a[2 * k]     = fmaf(f.x, w, a[2 * k]);
            a[2 * k + 1] = fmaf(f.y, w, a[2 * k + 1]);
        }
    };

    int i = beg;
    for (; i + 3 < end; i += 4) {
        int s0 = __ldg(&g_esrc[i]),     s1 = __ldg(&g_esrc[i + 1]);
        int s2 = __ldg(&g_esrc[i + 2]), s3 = __ldg(&g_esrc[i + 3]);
        float w0 = __ldg(&g_ew[i]),     w1 = __ldg(&g_ew[i + 1]);
        float w2 = __ldg(&g_ew[i + 2]), w3 = __ldg(&g_ew[i + 3]);
        uint4 q0 = __ldg(&Hv[(size_t)s0 * 32 + lane]);
        uint4 q1 = __ldg(&Hv[(size_t)s1 * 32 + lane]);
        uint4 q2 = __ldg(&Hv[(size_t)s2 * 32 + lane]);
        uint4 q3 = __ldg(&Hv[(size_t)s3 * 32 + lane]);
        acc8(a0, q0, w0); acc8(a1, q1, w1);
        acc8(a0, q2, w2); acc8(a1, q3, w3);
    }
    for (; i < end; i++) {
        int s0 = __ldg(&g_esrc[i]);
        float w0 = __ldg(&g_ew[i]);
        uint4 q0 = __ldg(&Hv[(size_t)s0 * 32 + lane]);
        acc8(a0, q0, w0);
    }
#pragma unroll
    for (int k = 0; k < 8; k++) a0[k] += a1[k];

    float nd = g_ndst[node];
    float4 bl = __ldg((const float4*)(bias + lane * 8));
    float4 bh = __ldg((const float4*)(bias + lane * 8 + 4));
    float4 r0, r1;
    r0.x = fmaxf(a0[0] * nd + bl.x, 0.f); r0.y = fmaxf(a0[1] * nd + bl.y, 0.f);
    r0.z = fmaxf(a0[2] * nd + bl.z, 0.f); r0.w = fmaxf(a0[3] * nd + bl.w, 0.f);
    r1.x = fmaxf(a0[4] * nd + bh.x, 0.f); r1.y = fmaxf(a0[5] * nd + bh.y, 0.f);
    r1.z = fmaxf(a0[6] * nd + bh.z, 0.f); r1.w = fmaxf(a0[7] * nd + bh.w, 0.f);
    *(float4*)(out + (size_t)node * 256 + lane * 8)     = r0;
    *(float4*)(out + (size_t)node * 256 + lane * 8 + 4) = r1;
}

// ---------------- agg2 (F=64, fp16 gather): 8 threads/node -----------------
__global__ void k_agg64h(const __half* __restrict__ H, const float* __restrict__ bias,
                         float* __restrict__ out, int N) {
    int node = blockIdx.x * 32 + (threadIdx.x >> 3);
    int t    = threadIdx.x & 7;
    if (node >= N) return;

    int beg = g_row_start[node];
    int end = g_row_start[node + 1];

    const uint4* Hv = (const uint4*)H;           // 8 uint4 per row
    float a0[8], a1[8];
#pragma unroll
    for (int k = 0; k < 8; k++) { a0[k] = 0.f; a1[k] = 0.f; }

    auto acc8 = [](float* a, uint4 q, float w) {
        __half2* h = (__half2*)&q;
#pragma unroll
        for (int k = 0; k < 4; k++) {
            float2 f = __half22float2(h[k]);
            a[2 * k]     = fmaf(f.x, w, a[2 * k]);
            a[2 * k + 1] = fmaf(f.y, w, a[2 * k + 1]);
        }
    };

    int i = beg;
    for (; i + 3 < end; i += 4) {
        int s0 = __ldg(&g_esrc[i]),     s1 = __ldg(&g_esrc[i + 1]);
        int s2 = __ldg(&g_esrc[i + 2]), s3 = __ldg(&g_esrc[i + 3]);
        float w0 = __ldg(&g_ew[i]),     w1 = __ldg(&g_ew[i + 1]);
        float w2 = __ldg(&g_ew[i + 2]), w3 = __ldg(&g_ew[i + 3]);
        uint4 q0 = __ldg(&Hv[(size_t)s0 * 8 + t]);
        uint4 q1 = __ldg(&Hv[(size_t)s1 * 8 + t]);
        uint4 q2 = __ldg(&Hv[(size_t)s2 * 8 + t]);
        uint4 q3 = __ldg(&Hv[(size_t)s3 * 8 + t]);
        acc8(a0, q0, w0); acc8(a1, q1, w1);
        acc8(a0, q2, w2); acc8(a1, q3, w3);
    }
    for (; i < end; i++) {
        int s0 = __ldg(&g_esrc[i]);
        float w0 = __ldg(&g_ew[i]);
        uint4 q0 = __ldg(&Hv[(size_t)s0 * 8 + t]);
        acc8(a0, q0, w0);
    }
#pragma unroll
    for (int k = 0; k < 8; k++) a0[k] += a1[k];

    float nd = g_ndst[node];
    float4 bl = __ldg((const float4*)(bias + t * 8));
    float4 bh = __ldg((const float4*)(bias + t * 8 + 4));
    float4 r0, r1;
    r0.x = a0[0] * nd + bl.x; r0.y = a0[1] * nd + bl.y;
    r0.z = a0[2] * nd + bl.z; r0.w = a0[3] * nd + bl.w;
    r1.x = a0[4] * nd + bh.x; r1.y = a0[5] * nd + bh.y;
    r1.z = a0[6] * nd + bh.z; r1.w = a0[7] * nd + bh.w;
    *(float4*)(out + (size_t)node * 64 + t * 8)     = r0;
    *(float4*)(out + (size_t)node * 64 + t * 8 + 4) = r1;
}

// ---------------- launch ----------------------------------------------------
extern "C" void kernel_launch(void* const* d_in, const int* in_sizes, int n_in,
                              void* d_out, int out_size) {
    const float* feat = (const float*)d_in[0];
    const int*   src  = (const int*)  d_in[1];
    const int*   dst  = (const int*)  d_in[2];
    const float* W1   = (const float*)d_in[3];
    const float* b1   = (const float*)d_in[4];
    const float* W2   = (const float*)d_in[5];
    const float* b2   = (const float*)d_in[6];
    float* out = (float*)d_out;

    const int N = in_sizes[0] / K1;   // 50000
    const int E = in_sizes[1];        // 800000

    void *p_H1h, *p_A1, *p_H2h;
    cudaGetSymbolAddress(&p_H1h, g_H1h);
    cudaGetSymbolAddress(&p_A1,  g_A1);
    cudaGetSymbolAddress(&p_H2h, g_H2h);

    const int T = 256;
    const int nb = (N + SCANB - 1) / SCANB;

    // 1) init + degrees + norms + 3-phase scan + CSR fill
    k_init <<<(N + T - 1) / T, T>>>(N);
    k_deg  <<<(E + T - 1) / T, T>>>(src, dst, E);
    k_norm <<<(N + T - 1) / T, T>>>(N);
    k_scan1<<<nb, SCANB>>>(N);
    k_scan2<<<1, SCANB>>>(nb);
    k_scan3<<<nb, SCANB>>>(N);
    k_fill <<<(E + T - 1) / T, T>>>(src, dst, E);

    // 2) GEMM1 (TF32 wmma, half out): H1h = half(feat @ W1)
    {
        dim3 grid((N + 127) / 128, F1 / 128);
        gemm_wmma_h<<<grid, 256>>>(feat, W1, (__half*)p_H1h, N, K1, F1);
    }

    // 3) agg1: A1 = relu(ndst * sum_e ew*H1h[src] + b1)   (fp32 accum/out)
    k_agg256h<<<(N + 7) / 8, 256>>>((const __half*)p_H1h, b1, (float*)p_A1, N);

    // 4) GEMM2 (fp32 SIMT, half out): H2h = half(A1 @ W2)
    {
        dim3 grid((N + 127) / 128, 1);
        sgemm_h<128, 64, 16, 8, 4><<<grid, 256>>>((const float*)p_A1, W2, (__half*)p_H2h, N, F1, F2);
    }

    // 5) agg2 -> d_out (fp32)
    k_agg64h<<<(N + 31) / 32, 256>>>((const __half*)p_H2h, b2, out, N);
}

// round 13
// speedup vs baseline: 1.2019x; 1.2019x over previous
#include <cuda_runtime.h>
#include <math.h>
#include <stdint.h>
#include <mma.h>

using namespace nvcuda;

#define NMAX   50000
#define NPAD   50048               // ceil(50000/128)*128 for unmasked wmma stores
#define EMAX   800000
#define K1     512
#define F1     256
#define F2     64
#define SCANB  256

// ---------------- scratch (static device globals) --------------------------
__device__ int   g_deg_out[NMAX];
__device__ int   g_deg_in [NMAX];
__device__ int   g_cursor [NMAX];
__device__ int   g_row_start[NMAX + 1];
__device__ int   g_part[SCANB];
__device__ int   g_esrc[EMAX];
__device__ float g_ew  [EMAX];              // nsrc[src[e]] per bucketed edge
__device__ float g_nsrc[NMAX];
__device__ float g_ndst[NMAX];
__device__ float g_H1[(size_t)NPAD * F1];   // padded: wmma stores full tiles
__device__ float g_A1[(size_t)NMAX * F1];
__device__ float g_H2[(size_t)NMAX * F2];

// ---------------- fused init ------------------------------------------------
__global__ void k_init(int n) {
    int i = blockIdx.x * blockDim.x + threadIdx.x;
    if (i < n) { g_deg_out[i] = 0; g_deg_in[i] = 0; g_cursor[i] = 0; }
}

// ---------------- degrees / norms ------------------------------------------
__global__ void k_deg(const int* __restrict__ src, const int* __restrict__ dst, int E) {
    int e = blockIdx.x * blockDim.x + threadIdx.x;
    if (e < E) {
        atomicAdd(&g_deg_out[src[e]], 1);
        atomicAdd(&g_deg_in [dst[e]], 1);
    }
}

__global__ void k_norm(int n) {
    int i = blockIdx.x * blockDim.x + threadIdx.x;
    if (i < n) {
        int o = g_deg_out[i], d = g_deg_in[i];
        g_nsrc[i] = (o > 0) ? rsqrtf((float)o) : 1.0f;
        g_ndst[i] = (d > 0) ? rsqrtf((float)d) : 1.0f;
    }
}

// ---------------- 3-phase multi-block scan: deg_in -> row_start -------------
__device__ __forceinline__ int warp_incl_scan(int v) {
#pragma unroll
    for (int off = 1; off < 32; off <<= 1) {
        int t = __shfl_up_sync(0xFFFFFFFFu, v, off);
        if ((threadIdx.x & 31) >= off) v += t;
    }
    return v;
}

__global__ void k_scan1(int n) {
    int i = blockIdx.x * SCANB + threadIdx.x;
    int v = (i < n) ? g_deg_in[i] : 0;
    int s = v;
#pragma unroll
    for (int off = 16; off > 0; off >>= 1) s += __shfl_down_sync(0xFFFFFFFFu, s, off);
    __shared__ int ws[SCANB / 32];
    if ((threadIdx.x & 31) == 0) ws[threadIdx.x >> 5] = s;
    __syncthreads();
    if (threadIdx.x == 0) {
        int t = 0;
#pragma unroll
        for (int w = 0; w < SCANB / 32; w++) t += ws[w];
        g_part[blockIdx.x] = t;
    }
}

__global__ void k_scan2(int nb) {
    int v = (threadIdx.x < nb) ? g_part[threadIdx.x] : 0;
    int s = warp_incl_scan(v);
    __shared__ int ws[SCANB / 32];
    if ((threadIdx.x & 31) == 31) ws[threadIdx.x >> 5] = s;
    __syncthreads();
    if (threadIdx.x < 32) {
        int w = (threadIdx.x < SCANB / 32) ? ws[threadIdx.x] : 0;
        int sw = warp_incl_scan(w);
        if (threadIdx.x < SCANB / 32) ws[threadIdx.x] = sw;
    }
    __syncthreads();
    int incl = s + ((threadIdx.x >= 32) ? ws[(threadIdx.x >> 5) - 1] : 0);
    if (threadIdx.x < nb) g_part[threadIdx.x] = incl - v;
}

__global__ void k_scan3(int n) {
    int i = blockIdx.x * SCANB + threadIdx.x;
    int v = (i < n) ? g_deg_in[i] : 0;
    int s = warp_incl_scan(v);
    __shared__ int ws[SCANB / 32];
    if ((threadIdx.x & 31) == 31) ws[threadIdx.x >> 5] = s;
    __syncthreads();
    if (threadIdx.x < 32) {
        int w = (threadIdx.x < SCANB / 32) ? ws[threadIdx.x] : 0;
        int sw = warp_incl_scan(w);
        if (threadIdx.x < SCANB / 32) ws[threadIdx.x] = sw;
    }
    __syncthreads();
    int incl = s + ((threadIdx.x >= 32) ? ws[(threadIdx.x >> 5) - 1] : 0);
    int off = g_part[blockIdx.x];
    if (i < n) g_row_start[i] = off + incl - v;
    if (i == n - 1) g_row_start[n] = off + incl;
}

// ---------------- bucket edges by dst --------------------------------------
__global__ void k_fill(const int* __restrict__ src, const int* __restrict__ dst, int E) {
    int e = blockIdx.x * blockDim.x + threadIdx.x;
    if (e < E) {
        int s = src[e];
        int d = dst[e];
        int pos = g_row_start[d] + atomicAdd(&g_cursor[d], 1);
        g_esrc[pos] = s;
        g_ew [pos] = g_nsrc[s];
    }
}

// ---------------- TF32 wmma GEMM (GEMM1):  C = A @ B, C rows padded --------
__global__ void __launch_bounds__(256) gemm_wmma(
    const float* __restrict__ A, const float* __restrict__ B,
    float* __restrict__ C, int M, int K, int N) {
    constexpr int BM = 128, BN = 128, BK = 16;
    constexpr int AST = BK + 4;
    constexpr int BST = BN + 4;
    __shared__ float As[2][BM * AST];
    __shared__ float Bs[2][BK * BST];

    const int tid = threadIdx.x;
    const int wid = tid >> 5;
    const int wm  = (wid & 1) * 64;
    const int wn  = (wid >> 1) * 32;
    const int bm  = blockIdx.x * BM;
    const int bn  = blockIdx.y * BN;

    wmma::fragment<wmma::accumulator, 16, 16, 8, float> fc[4][2];
#pragma unroll
    for (int i = 0; i < 4; i++)
#pragma unroll
        for (int j = 0; j < 2; j++) wmma::fill_fragment(fc[i][j], 0.0f);

    float4 ra[2], rb[2];

    auto loadA = [&](int k0) {
#pragma unroll
        for (int u = 0; u < 2; u++) {
            int idx = tid + u * 256;
            int m   = idx >> 2;
            int kq  = idx & 3;
            int gm  = bm + m;
            float4 v = make_float4(0.f, 0.f, 0.f, 0.f);
            if (gm < M) v = *(const float4*)(A + (size_t)gm * K + k0 + kq * 4);
            ra[u] = v;
        }
    };
    auto loadB = [&](int k0) {
#pragma unroll
        for (int u = 0; u < 2; u++) {
            int idx = tid + u * 256;
            int k   = idx >> 5;
            int n4  = idx & 31;
            rb[u] = *(const float4*)(B + (size_t)(k0 + k) * N + bn + n4 * 4);
        }
    };
    auto stage = [&](int st) {
#pragma unroll
        for (int u = 0; u < 2; u++) {
            int idx = tid + u * 256;
            int m = idx >> 2, kq = idx & 3;
            float* p = &As[st][m * AST + kq * 4];
            p[0] = wmma::__float_to_tf32(ra[u].x);
            p[1] = wmma::__float_to_tf32(ra[u].y);
            p[2] = wmma::__float_to_tf32(ra[u].z);
            p[3] = wmma::__float_to_tf32(ra[u].w);
        }
#pragma unroll
        for (int u = 0; u < 2; u++) {
            int idx = tid + u * 256;
            int k = idx >> 5, n4 = idx & 31;
            float* p = &Bs[st][k * BST + n4 * 4];
            p[0] = wmma::__float_to_tf32(rb[u].x);
            p[1] = wmma::__float_to_tf32(rb[u].y);
            p[2] = wmma::__float_to_tf32(rb[u].z);
            p[3] = wmma::__float_to_tf32(rb[u].w);
        }
    };

    loadA(0); loadB(0);
    stage(0);
    __syncthreads();

    const int nt = K / BK;
    for (int t = 0; t < nt; t++) {
        int st = t & 1;
        if (t + 1 < nt) { loadA((t + 1) * BK); loadB((t + 1) * BK); }

#pragma unroll
        for (int ks = 0; ks < BK; ks += 8) {
            wmma::fragment<wmma::matrix_a, 16, 16, 8, wmma::precision::tf32, wmma::row_major> fa[4];
            wmma::fragment<wmma::matrix_b, 16, 16, 8, wmma::precision::tf32, wmma::row_major> fb[2];
#pragma unroll
            for (int i = 0; i < 4; i++)
                wmma::load_matrix_sync(fa[i], &As[st][(wm + i * 16) * AST + ks], AST);
#pragma unroll
            for (int j = 0; j < 2; j++)
                wmma::load_matrix_sync(fb[j], &Bs[st][ks * BST + wn + j * 16], BST);
#pragma unroll
            for (int i = 0; i < 4; i++)
#pragma unroll
                for (int j = 0; j < 2; j++)
                    wmma::mma_sync(fc[i][j], fa[i], fb[j], fc[i][j]);
        }

        if (t + 1 < nt) { stage(st ^ 1); }
        __syncthreads();
    }

#pragma unroll
    for (int i = 0; i < 4; i++)
#pragma unroll
        for (int j = 0; j < 2; j++)
            wmma::store_matrix_sync(
                C + (size_t)(bm + wm + i * 16) * N + bn + wn + j * 16,
                fc[i][j], N, wmma::mem_row_major);
}

// ---------------- fp32 SIMT SGEMM (GEMM2, exact) ---------------------------
template<int BM, int BN, int BK, int TM, int TN>
__global__ void sgemm(const float* __restrict__ A, const float* __restrict__ B,
                      float* __restrict__ C, int M, int K, int N) {
    constexpr int NT  = (BM / TM) * (BN / TN);
    constexpr int ASS = BM + 4;
    __shared__ float As[BK][ASS];
    __shared__ float Bs[BK][BN];

    const int tid  = threadIdx.x;
    const int bm   = blockIdx.x * BM;
    const int bn   = blockIdx.y * BN;
    const int tcol = tid % (BN / TN);
    const int trow = tid / (BN / TN);

    float acc[TM][TN];
#pragma unroll
    for (int i = 0; i < TM; i++)
#pragma unroll
        for (int j = 0; j < TN; j++) acc[i][j] = 0.0f;

    constexpr int AF4 = BM * BK / 4;
    constexpr int BF4 = BK * BN / 4;

    for (int k0 = 0; k0 < K; k0 += BK) {
#pragma unroll
        for (int idx = tid; idx < AF4; idx += NT) {
            int m  = idx / (BK / 4);
            int kk = (idx % (BK / 4)) * 4;
            int gm = bm + m;
            float4 v = make_float4(0.f, 0.f, 0.f, 0.f);
            if (gm < M) v = *(const float4*)(A + (size_t)gm * K + k0 + kk);
            As[kk + 0][m] = v.x; As[kk + 1][m] = v.y;
            As[kk + 2][m] = v.z; As[kk + 3][m] = v.w;
        }
#pragma unroll
        for (int idx = tid; idx < BF4; idx += NT) {
            int k  = idx / (BN / 4);
            int n4 = idx % (BN / 4);
            *(float4*)&Bs[k][n4 * 4] =
                *(const float4*)(B + (size_t)(k0 + k) * N + bn + n4 * 4);
        }
        __syncthreads();

#pragma unroll
        for (int k = 0; k < BK; k++) {
            float ra[TM], rb[TN];
#pragma unroll
            for (int i = 0; i < TM; i += 4) {
                float4 t = *(const float4*)&As[k][trow * TM + i];
                ra[i] = t.x; ra[i + 1] = t.y; ra[i + 2] = t.z; ra[i + 3] = t.w;
            }
#pragma unroll
            for (int j = 0; j < TN; j += 4) {
                float4 t = *(const float4*)&Bs[k][tcol * TN + j];
                rb[j] = t.x; rb[j + 1] = t.y; rb[j + 2] = t.z; rb[j + 3] = t.w;
            }
#pragma unroll
            for (int i = 0; i < TM; i++)
#pragma unroll
                for (int j = 0; j < TN; j++)
                    acc[i][j] = fmaf(ra[i], rb[j], acc[i][j]);
        }
        __syncthreads();
    }

#pragma unroll
    for (int i = 0; i < TM; i++) {
        int gm = bm + trow * TM + i;
        if (gm < M) {
#pragma unroll
            for (int j = 0; j < TN; j += 4) {
                float4 t = make_float4(acc[i][j], acc[i][j + 1], acc[i][j + 2], acc[i][j + 3]);
                *(float4*)(C + (size_t)gm * N + bn + tcol * TN + j) = t;
            }
        }
    }
}

// ---------------- agg F=256: one warp/node, 4-edge unroll (8 loads deep) ---
__global__ void k_agg256(const float* __restrict__ H, const float* __restrict__ bias,
                         float* __restrict__ out, int N) {
    int node = blockIdx.x * 8 + (threadIdx.x >> 5);
    int lane = threadIdx.x & 31;
    if (node >= N) return;

    int beg = g_row_start[node];
    int end = g_row_start[node + 1];

    const float4* Hv = (const float4*)H;   // 64 float4 per row
    float4 lo0 = {0,0,0,0}, hi0 = {0,0,0,0};
    float4 lo1 = {0,0,0,0}, hi1 = {0,0,0,0};

    int i = beg;
    for (; i + 3 < end; i += 4) {
        int   s0 = __ldg(&g_esrc[i]),     s1 = __ldg(&g_esrc[i + 1]);
        int   s2 = __ldg(&g_esrc[i + 2]), s3 = __ldg(&g_esrc[i + 3]);
        float w0 = __ldg(&g_ew[i]),       w1 = __ldg(&g_ew[i + 1]);
        float w2 = __ldg(&g_ew[i + 2]),   w3 = __ldg(&g_ew[i + 3]);
        // 8 independent 16B loads in flight
        float4 a = __ldg(&Hv[(size_t)s0 * 64 + lane]);
        float4 b = __ldg(&Hv[(size_t)s0 * 64 + lane + 32]);
        float4 c = __ldg(&Hv[(size_t)s1 * 64 + lane]);
        float4 d = __ldg(&Hv[(size_t)s1 * 64 + lane + 32]);
        float4 e = __ldg(&Hv[(size_t)s2 * 64 + lane]);
        float4 f = __ldg(&Hv[(size_t)s2 * 64 + lane + 32]);
        float4 g = __ldg(&Hv[(size_t)s3 * 64 + lane]);
        float4 h = __ldg(&Hv[(size_t)s3 * 64 + lane + 32]);
        lo0.x = fmaf(a.x, w0, lo0.x); lo0.y = fmaf(a.y, w0, lo0.y);
        lo0.z = fmaf(a.z, w0, lo0.z); lo0.w = fmaf(a.w, w0, lo0.w);
        hi0.x = fmaf(b.x, w0, hi0.x); hi0.y = fmaf(b.y, w0, hi0.y);
        hi0.z = fmaf(b.z, w0, hi0.z); hi0.w = fmaf(b.w, w0, hi0.w);
        lo1.x = fmaf(c.x, w1, lo1.x); lo1.y = fmaf(c.y, w1, lo1.y);
        lo1.z = fmaf(c.z, w1, lo1.z); lo1.w = fmaf(c.w, w1, lo1.w);
        hi1.x = fmaf(d.x, w1, hi1.x); hi1.y = fmaf(d.y, w1, hi1.y);
        hi1.z = fmaf(d.z, w1, hi1.z); hi1.w = fmaf(d.w, w1, hi1.w);
        lo0.x = fmaf(e.x, w2, lo0.x); lo0.y = fmaf(e.y, w2, lo0.y);
        lo0.z = fmaf(e.z, w2, lo0.z); lo0.w = fmaf(e.w, w2, lo0.w);
        hi0.x = fmaf(f.x, w2, hi0.x); hi0.y = fmaf(f.y, w2, hi0.y);
        hi0.z = fmaf(f.z, w2, hi0.z); hi0.w = fmaf(f.w, w2, hi0.w);
        lo1.x = fmaf(g.x, w3, lo1.x); lo1.y = fmaf(g.y, w3, lo1.y);
        lo1.z = fmaf(g.z, w3, lo1.z); lo1.w = fmaf(g.w, w3, lo1.w);
        hi1.x = fmaf(h.x, w3, hi1.x); hi1.y = fmaf(h.y, w3, hi1.y);
        hi1.z = fmaf(h.z, w3, hi1.z); hi1.w = fmaf(h.w, w3, hi1.w);
    }
    for (; i < end; i++) {
        int   s0 = __ldg(&g_esrc[i]);
        float w0 = __ldg(&g_ew[i]);
        float4 a = __ldg(&Hv[(size_t)s0 * 64 + lane]);
        float4 b = __ldg(&Hv[(size_t)s0 * 64 + lane + 32]);
        lo0.x = fmaf(a.x, w0, lo0.x); lo0.y = fmaf(a.y, w0, lo0.y);
        lo0.z = fmaf(a.z, w0, lo0.z); lo0.w = fmaf(a.w, w0, lo0.w);
        hi0.x = fmaf(b.x, w0, hi0.x); hi0.y = fmaf(b.y, w0, hi0.y);
        hi0.z = fmaf(b.z, w0, hi0.z); hi0.w = fmaf(b.w, w0, hi0.w);
    }
    lo0.x += lo1.x; lo0.y += lo1.y; lo0.z += lo1.z; lo0.w += lo1.w;
    hi0.x += hi1.x; hi0.y += hi1.y; hi0.z += hi1.z; hi0.w += hi1.w;

    float nd = g_ndst[node];
    float4 bl = __ldg(&((const float4*)bias)[lane]);
    float4 bh = __ldg(&((const float4*)bias)[lane + 32]);
    float4 rl, rh;
    rl.x = fmaxf(lo0.x * nd + bl.x, 0.f); rl.y = fmaxf(lo0.y * nd + bl.y, 0.f);
    rl.z = fmaxf(lo0.z * nd + bl.z, 0.f); rl.w = fmaxf(lo0.w * nd + bl.w, 0.f);
    rh.x = fmaxf(hi0.x * nd + bh.x, 0.f); rh.y = fmaxf(hi0.y * nd + bh.y, 0.f);
    rh.z = fmaxf(hi0.z * nd + bh.z, 0.f); rh.w = fmaxf(hi0.w * nd + bh.w, 0.f);
    ((float4*)out)[(size_t)node * 64 + lane]      = rl;
    ((float4*)out)[(size_t)node * 64 + lane + 32] = rh;
}

// ---------------- agg F=64: 16 threads/node, 4-way unroll ------------------
__global__ void k_agg64(const float* __restrict__ H, const float* __restrict__ bias,
                        float* __restrict__ out, int N) {
    int node = blockIdx.x * 16 + (threadIdx.x >> 4);
    int lane = threadIdx.x & 15;
    if (node >= N) return;

    int beg = g_row_start[node];
    int end = g_row_start[node + 1];

    const float4* Hv = (const float4*)H;
    float4 a0 = {0,0,0,0}, a1 = {0,0,0,0}, a2 = {0,0,0,0}, a3 = {0,0,0,0};

    int i = beg;
    for (; i + 3 < end; i += 4) {
        int s0 = __ldg(&g_esrc[i]),     s1 = __ldg(&g_esrc[i + 1]);
        int s2 = __ldg(&g_esrc[i + 2]), s3 = __ldg(&g_esrc[i + 3]);
        float w0 = __ldg(&g_ew[i]),     w1 = __ldg(&g_ew[i + 1]);
        float w2 = __ldg(&g_ew[i + 2]), w3 = __ldg(&g_ew[i + 3]);
        float4 v0 = __ldg(&Hv[(size_t)s0 * 16 + lane]);
        float4 v1 = __ldg(&Hv[(size_t)s1 * 16 + lane]);
        float4 v2 = __ldg(&Hv[(size_t)s2 * 16 + lane]);
        float4 v3 = __ldg(&Hv[(size_t)s3 * 16 + lane]);
        a0.x = fmaf(v0.x, w0, a0.x); a0.y = fmaf(v0.y, w0, a0.y);
        a0.z = fmaf(v0.z, w0, a0.z); a0.w = fmaf(v0.w, w0, a0.w);
        a1.x = fmaf(v1.x, w1, a1.x); a1.y = fmaf(v1.y, w1, a1.y);
        a1.z = fmaf(v1.z, w1, a1.z); a1.w = fmaf(v1.w, w1, a1.w);
        a2.x = fmaf(v2.x, w2, a2.x); a2.y = fmaf(v2.y, w2, a2.y);
        a2.z = fmaf(v2.z, w2, a2.z); a2.w = fmaf(v2.w, w2, a2.w);
        a3.x = fmaf(v3.x, w3, a3.x); a3.y = fmaf(v3.y, w3, a3.y);
        a3.z = fmaf(v3.z, w3, a3.z); a3.w = fmaf(v3.w, w3, a3.w);
    }
    for (; i < end; i++) {
        int s0 = __ldg(&g_esrc[i]);
        float w0 = __ldg(&g_ew[i]);
        float4 v0 = __ldg(&Hv[(size_t)s0 * 16 + lane]);
        a0.x = fmaf(v0.x, w0, a0.x); a0.y = fmaf(v0.y, w0, a0.y);
        a0.z = fmaf(v0.z, w0, a0.z); a0.w = fmaf(v0.w, w0, a0.w);
    }
    a0.x += a1.x + a2.x + a3.x; a0.y += a1.y + a2.y + a3.y;
    a0.z += a1.z + a2.z + a3.z; a0.w += a1.w + a2.w + a3.w;

    float nd = g_ndst[node];
    float4 b = __ldg(&((const float4*)bias)[lane]);
    float4 r;
    r.x = a0.x * nd + b.x; r.y = a0.y * nd + b.y;
    r.z = a0.z * nd + b.z; r.w = a0.w * nd + b.w;
    ((float4*)out)[(size_t)node * 16 + lane] = r;
}

// ---------------- launch ----------------------------------------------------
extern "C" void kernel_launch(void* const* d_in, const int* in_sizes, int n_in,
                              void* d_out, int out_size) {
    const float* feat = (const float*)d_in[0];
    const int*   src  = (const int*)  d_in[1];
    const int*   dst  = (const int*)  d_in[2];
    const float* W1   = (const float*)d_in[3];
    const float* b1   = (const float*)d_in[4];
    const float* W2   = (const float*)d_in[5];
    const float* b2   = (const float*)d_in[6];
    float* out = (float*)d_out;

    const int N = in_sizes[0] / K1;   // 50000
    const int E = in_sizes[1];        // 800000

    void *p_H1, *p_A1, *p_H2;
    cudaGetSymbolAddress(&p_H1, g_H1);
    cudaGetSymbolAddress(&p_A1, g_A1);
    cudaGetSymbolAddress(&p_H2, g_H2);

    const int T = 256;
    const int nb = (N + SCANB - 1) / SCANB;

    // 1) init + degrees + norms + 3-phase scan + CSR fill  (R9 sequence)
    k_init <<<(N + T - 1) / T, T>>>(N);
    k_deg  <<<(E + T - 1) / T, T>>>(src, dst, E);
    k_norm <<<(N + T - 1) / T, T>>>(N);
    k_scan1<<<nb, SCANB>>>(N);
    k_scan2<<<1, SCANB>>>(nb);
    k_scan3<<<nb, SCANB>>>(N);
    k_fill <<<(E + T - 1) / T, T>>>(src, dst, E);

    // 2) GEMM1 (TF32 wmma): H1 = feat @ W1
    {
        dim3 grid((N + 127) / 128, F1 / 128);
        gemm_wmma<<<grid, 256>>>(feat, W1, (float*)p_H1, N, K1, F1);
    }

    // 3) aggregate layer 1: A1 = relu(ndst * sum_e ew*H1[src] + b1)
    k_agg256<<<(N + 7) / 8, 256>>>((const float*)p_H1, b1, (float*)p_A1, N);

    // 4) GEMM2 (exact fp32 SIMT): H2 = A1 @ W2
    {
        dim3 grid((N + 127) / 128, 1);
        sgemm<128, 64, 16, 8, 4><<<grid, 256>>>((const float*)p_A1, W2, (float*)p_H2, N, F1, F2);
    }

    // 5) aggregate layer 2 -> d_out
    k_agg64<<<(N + 15) / 16, 256>>>((const float*)p_H2, b2, out, N);
}

// round 14
// speedup vs baseline: 1.2020x; 1.0001x over previous
#include <cuda_runtime.h>
#include <math.h>
#include <stdint.h>
#include <mma.h>

using namespace nvcuda;

#define NMAX   50000
#define NPAD   50048               // ceil(50000/128)*128 for unmasked wmma stores
#define EMAX   800000
#define K1     512
#define F1     256
#define F2     64
#define SCANB  256

// ---------------- scratch (static device globals) --------------------------
__device__ int   g_deg_out[NMAX];
__device__ int   g_deg_in [NMAX];
__device__ int   g_cursor [NMAX];
__device__ int   g_row_start[NMAX + 1];
__device__ int   g_part[SCANB];
__device__ int   g_esrc[EMAX];
__device__ float g_ew  [EMAX];              // nsrc[src[e]] per bucketed edge
__device__ float g_nsrc[NMAX];
__device__ float g_ndst[NMAX];
__device__ float g_H1[(size_t)NPAD * F1];   // padded: wmma stores full tiles
__device__ float g_A1[(size_t)NMAX * F1];
__device__ float g_H2[(size_t)NMAX * F2];

// ---------------- fused init ------------------------------------------------
__global__ void k_init(int n) {
    int i = blockIdx.x * blockDim.x + threadIdx.x;
    if (i < n) { g_deg_out[i] = 0; g_deg_in[i] = 0; g_cursor[i] = 0; }
}

// ---------------- degrees ---------------------------------------------------
__global__ void k_deg(const int* __restrict__ src, const int* __restrict__ dst, int E) {
    int e = blockIdx.x * blockDim.x + threadIdx.x;
    if (e < E) {
        atomicAdd(&g_deg_out[src[e]], 1);
        atomicAdd(&g_deg_in [dst[e]], 1);
    }
}

// ---------------- scan phase 1 (+ fused norm computation) -------------------
__device__ __forceinline__ int warp_incl_scan(int v) {
#pragma unroll
    for (int off = 1; off < 32; off <<= 1) {
        int t = __shfl_up_sync(0xFFFFFFFFu, v, off);
        if ((threadIdx.x & 31) >= off) v += t;
    }
    return v;
}

__global__ void k_scan1(int n) {
    int i = blockIdx.x * SCANB + threadIdx.x;
    int v = 0;
    if (i < n) {
        int o = g_deg_out[i];
        v = g_deg_in[i];
        g_nsrc[i] = (o > 0) ? rsqrtf((float)o) : 1.0f;
        g_ndst[i] = (v > 0) ? rsqrtf((float)v) : 1.0f;
    }
    int s = v;
#pragma unroll
    for (int off = 16; off > 0; off >>= 1) s += __shfl_down_sync(0xFFFFFFFFu, s, off);
    __shared__ int ws[SCANB / 32];
    if ((threadIdx.x & 31) == 0) ws[threadIdx.x >> 5] = s;
    __syncthreads();
    if (threadIdx.x == 0) {
        int t = 0;
#pragma unroll
        for (int w = 0; w < SCANB / 32; w++) t += ws[w];
        g_part[blockIdx.x] = t;
    }
}

__global__ void k_scan2(int nb) {
    int v = (threadIdx.x < nb) ? g_part[threadIdx.x] : 0;
    int s = warp_incl_scan(v);
    __shared__ int ws[SCANB / 32];
    if ((threadIdx.x & 31) == 31) ws[threadIdx.x >> 5] = s;
    __syncthreads();
    if (threadIdx.x < 32) {
        int w = (threadIdx.x < SCANB / 32) ? ws[threadIdx.x] : 0;
        int sw = warp_incl_scan(w);
        if (threadIdx.x < SCANB / 32) ws[threadIdx.x] = sw;
    }
    __syncthreads();
    int incl = s + ((threadIdx.x >= 32) ? ws[(threadIdx.x >> 5) - 1] : 0);
    if (threadIdx.x < nb) g_part[threadIdx.x] = incl - v;
}

__global__ void k_scan3(int n) {
    int i = blockIdx.x * SCANB + threadIdx.x;
    int v = (i < n) ? g_deg_in[i] : 0;
    int s = warp_incl_scan(v);
    __shared__ int ws[SCANB / 32];
    if ((threadIdx.x & 31) == 31) ws[threadIdx.x >> 5] = s;
    __syncthreads();
    if (threadIdx.x < 32) {
        int w = (threadIdx.x < SCANB / 32) ? ws[threadIdx.x] : 0;
        int sw = warp_incl_scan(w);
        if (threadIdx.x < SCANB / 32) ws[threadIdx.x] = sw;
    }
    __syncthreads();
    int incl = s + ((threadIdx.x >= 32) ? ws[(threadIdx.x >> 5) - 1] : 0);
    int off = g_part[blockIdx.x];
    if (i < n) g_row_start[i] = off + incl - v;
    if (i == n - 1) g_row_start[n] = off + incl;
}

// ---------------- bucket edges by dst --------------------------------------
__global__ void k_fill(const int* __restrict__ src, const int* __restrict__ dst, int E) {
    int e = blockIdx.x * blockDim.x + threadIdx.x;
    if (e < E) {
        int s = src[e];
        int d = dst[e];
        int pos = g_row_start[d] + atomicAdd(&g_cursor[d], 1);
        g_esrc[pos] = s;
        g_ew [pos] = g_nsrc[s];
    }
}

// ---------------- TF32 wmma GEMM (GEMM1):  C = A @ B, C rows padded --------
__global__ void __launch_bounds__(256) gemm_wmma(
    const float* __restrict__ A, const float* __restrict__ B,
    float* __restrict__ C, int M, int K, int N) {
    constexpr int BM = 128, BN = 128, BK = 16;
    constexpr int AST = BK + 4;
    constexpr int BST = BN + 4;
    __shared__ float As[2][BM * AST];
    __shared__ float Bs[2][BK * BST];

    const int tid = threadIdx.x;
    const int wid = tid >> 5;
    const int wm  = (wid & 1) * 64;
    const int wn  = (wid >> 1) * 32;
    const int bm  = blockIdx.x * BM;
    const int bn  = blockIdx.y * BN;

    wmma::fragment<wmma::accumulator, 16, 16, 8, float> fc[4][2];
#pragma unroll
    for (int i = 0; i < 4; i++)
#pragma unroll
        for (int j = 0; j < 2; j++) wmma::fill_fragment(fc[i][j], 0.0f);

    float4 ra[2], rb[2];

    auto loadA = [&](int k0) {
#pragma unroll
        for (int u = 0; u < 2; u++) {
            int idx = tid + u * 256;
            int m   = idx >> 2;
            int kq  = idx & 3;
            int gm  = bm + m;
            float4 v = make_float4(0.f, 0.f, 0.f, 0.f);
            if (gm < M) v = *(const float4*)(A + (size_t)gm * K + k0 + kq * 4);
            ra[u] = v;
        }
    };
    auto loadB = [&](int k0) {
#pragma unroll
        for (int u = 0; u < 2; u++) {
            int idx = tid + u * 256;
            int k   = idx >> 5;
            int n4  = idx & 31;
            rb[u] = *(const float4*)(B + (size_t)(k0 + k) * N + bn + n4 * 4);
        }
    };
    auto stage = [&](int st) {
#pragma unroll
        for (int u = 0; u < 2; u++) {
            int idx = tid + u * 256;
            int m = idx >> 2, kq = idx & 3;
            float* p = &As[st][m * AST + kq * 4];
            p[0] = wmma::__float_to_tf32(ra[u].x);
            p[1] = wmma::__float_to_tf32(ra[u].y);
            p[2] = wmma::__float_to_tf32(ra[u].z);
            p[3] = wmma::__float_to_tf32(ra[u].w);
        }
#pragma unroll
        for (int u = 0; u < 2; u++) {
            int idx = tid + u * 256;
            int k = idx >> 5, n4 = idx & 31;
            float* p = &Bs[st][k * BST + n4 * 4];
            p[0] = wmma::__float_to_tf32(rb[u].x);
            p[1] = wmma::__float_to_tf32(rb[u].y);
            p[2] = wmma::__float_to_tf32(rb[u].z);
            p[3] = wmma::__float_to_tf32(rb[u].w);
        }
    };

    loadA(0); loadB(0);
    stage(0);
    __syncthreads();

    const int nt = K / BK;
    for (int t = 0; t < nt; t++) {
        int st = t & 1;
        if (t + 1 < nt) { loadA((t + 1) * BK); loadB((t + 1) * BK); }

#pragma unroll
        for (int ks = 0; ks < BK; ks += 8) {
            wmma::fragment<wmma::matrix_a, 16, 16, 8, wmma::precision::tf32, wmma::row_major> fa[4];
            wmma::fragment<wmma::matrix_b, 16, 16, 8, wmma::precision::tf32, wmma::row_major> fb[2];
#pragma unroll
            for (int i = 0; i < 4; i++)
                wmma::load_matrix_sync(fa[i], &As[st][(wm + i * 16) * AST + ks], AST);
#pragma unroll
            for (int j = 0; j < 2; j++)
                wmma::load_matrix_sync(fb[j], &Bs[st][ks * BST + wn + j * 16], BST);
#pragma unroll
            for (int i = 0; i < 4; i++)
#pragma unroll
                for (int j = 0; j < 2; j++)
                    wmma::mma_sync(fc[i][j], fa[i], fb[j], fc[i][j]);
        }

        if (t + 1 < nt) { stage(st ^ 1); }
        __syncthreads();
    }

#pragma unroll
    for (int i = 0; i < 4; i++)
#pragma unroll
        for (int j = 0; j < 2; j++)
            wmma::store_matrix_sync(
                C + (size_t)(bm + wm + i * 16) * N + bn + wn + j * 16,
                fc[i][j], N, wmma::mem_row_major);
}

// ---------------- fp32 SIMT SGEMM (GEMM2, exact) ---------------------------
template<int BM, int BN, int BK, int TM, int TN>
__global__ void sgemm(const float* __restrict__ A, const float* __restrict__ B,
                      float* __restrict__ C, int M, int K, int N) {
    constexpr int NT  = (BM / TM) * (BN / TN);
    constexpr int ASS = BM + 4;
    __shared__ float As[BK][ASS];
    __shared__ float Bs[BK][BN];

    const int tid  = threadIdx.x;
    const int bm   = blockIdx.x * BM;
    const int bn   = blockIdx.y * BN;
    const int tcol = tid % (BN / TN);
    const int trow = tid / (BN / TN);

    float acc[TM][TN];
#pragma unroll
    for (int i = 0; i < TM; i++)
#pragma unroll
        for (int j = 0; j < TN; j++) acc[i][j] = 0.0f;

    constexpr int AF4 = BM * BK / 4;
    constexpr int BF4 = BK * BN / 4;

    for (int k0 = 0; k0 < K; k0 += BK) {
#pragma unroll
        for (int idx = tid; idx < AF4; idx += NT) {
            int m  = idx / (BK / 4);
            int kk = (idx % (BK / 4)) * 4;
            int gm = bm + m;
            float4 v = make_float4(0.f, 0.f, 0.f, 0.f);
            if (gm < M) v = *(const float4*)(A + (size_t)gm * K + k0 + kk);
            As[kk + 0][m] = v.x; As[kk + 1][m] = v.y;
            As[kk + 2][m] = v.z; As[kk + 3][m] = v.w;
        }
#pragma unroll
        for (int idx = tid; idx < BF4; idx += NT) {
            int k  = idx / (BN / 4);
            int n4 = idx % (BN / 4);
            *(float4*)&Bs[k][n4 * 4] =
                *(const float4*)(B + (size_t)(k0 + k) * N + bn + n4 * 4);
        }
        __syncthreads();

#pragma unroll
        for (int k = 0; k < BK; k++) {
            float ra[TM], rb[TN];
#pragma unroll
            for (int i = 0; i < TM; i += 4) {
                float4 t = *(const float4*)&As[k][trow * TM + i];
                ra[i] = t.x; ra[i + 1] = t.y; ra[i + 2] = t.z; ra[i + 3] = t.w;
            }
#pragma unroll
            for (int j = 0; j < TN; j += 4) {
                float4 t = *(const float4*)&Bs[k][tcol * TN + j];
                rb[j] = t.x; rb[j + 1] = t.y; rb[j + 2] = t.z; rb[j + 3] = t.w;
            }
#pragma unroll
            for (int i = 0; i < TM; i++)
#pragma unroll
                for (int j = 0; j < TN; j++)
                    acc[i][j] = fmaf(ra[i], rb[j], acc[i][j]);
        }
        __syncthreads();
    }

#pragma unroll
    for (int i = 0; i < TM; i++) {
        int gm = bm + trow * TM + i;
        if (gm < M) {
#pragma unroll
            for (int j = 0; j < TN; j += 4) {
                float4 t = make_float4(acc[i][j], acc[i][j + 1], acc[i][j + 2], acc[i][j + 3]);
                *(float4*)(C + (size_t)gm * N + bn + tcol * TN + j) = t;
            }
        }
    }
}

// ---------------- agg F=256: one warp/node, 4-edge unroll (8 loads deep) ---
__global__ void k_agg256(const float* __restrict__ H, const float* __restrict__ bias,
                         float* __restrict__ out, int N) {
    int node = blockIdx.x * 8 + (threadIdx.x >> 5);
    int lane = threadIdx.x & 31;
    if (node >= N) return;

    int beg = g_row_start[node];
    int end = g_row_start[node + 1];

    const float4* Hv = (const float4*)H;   // 64 float4 per row
    float4 lo0 = {0,0,0,0}, hi0 = {0,0,0,0};
    float4 lo1 = {0,0,0,0}, hi1 = {0,0,0,0};

    int i = beg;
    for (; i + 3 < end; i += 4) {
        int   s0 = __ldg(&g_esrc[i]),     s1 = __ldg(&g_esrc[i + 1]);
        int   s2 = __ldg(&g_esrc[i + 2]), s3 = __ldg(&g_esrc[i + 3]);
        float w0 = __ldg(&g_ew[i]),       w1 = __ldg(&g_ew[i + 1]);
        float w2 = __ldg(&g_ew[i + 2]),   w3 = __ldg(&g_ew[i + 3]);
        float4 a = __ldg(&Hv[(size_t)s0 * 64 + lane]);
        float4 b = __ldg(&Hv[(size_t)s0 * 64 + lane + 32]);
        float4 c = __ldg(&Hv[(size_t)s1 * 64 + lane]);
        float4 d = __ldg(&Hv[(size_t)s1 * 64 + lane + 32]);
        float4 e = __ldg(&Hv[(size_t)s2 * 64 + lane]);
        float4 f = __ldg(&Hv[(size_t)s2 * 64 + lane + 32]);
        float4 g = __ldg(&Hv[(size_t)s3 * 64 + lane]);
        float4 h = __ldg(&Hv[(size_t)s3 * 64 + lane + 32]);
        lo0.x = fmaf(a.x, w0, lo0.x); lo0.y = fmaf(a.y, w0, lo0.y);
        lo0.z = fmaf(a.z, w0, lo0.z); lo0.w = fmaf(a.w, w0, lo0.w);
        hi0.x = fmaf(b.x, w0, hi0.x); hi0.y = fmaf(b.y, w0, hi0.y);
        hi0.z = fmaf(b.z, w0, hi0.z); hi0.w = fmaf(b.w, w0, hi0.w);
        lo1.x = fmaf(c.x, w1, lo1.x); lo1.y = fmaf(c.y, w1, lo1.y);
        lo1.z = fmaf(c.z, w1, lo1.z); lo1.w = fmaf(c.w, w1, lo1.w);
        hi1.x = fmaf(d.x, w1, hi1.x); hi1.y = fmaf(d.y, w1, hi1.y);
        hi1.z = fmaf(d.z, w1, hi1.z); hi1.w = fmaf(d.w, w1, hi1.w);
        lo0.x = fmaf(e.x, w2, lo0.x); lo0.y = fmaf(e.y, w2, lo0.y);
        lo0.z = fmaf(e.z, w2, lo0.z); lo0.w = fmaf(e.w, w2, lo0.w);
        hi0.x = fmaf(f.x, w2, hi0.x); hi0.y = fmaf(f.y, w2, hi0.y);
        hi0.z = fmaf(f.z, w2, hi0.z); hi0.w = fmaf(f.w, w2, hi0.w);
        lo1.x = fmaf(g.x, w3, lo1.x); lo1.y = fmaf(g.y, w3, lo1.y);
        lo1.z = fmaf(g.z, w3, lo1.z); lo1.w = fmaf(g.w, w3, lo1.w);
        hi1.x = fmaf(h.x, w3, hi1.x); hi1.y = fmaf(h.y, w3, hi1.y);
        hi1.z = fmaf(h.z, w3, hi1.z); hi1.w = fmaf(h.w, w3, hi1.w);
    }
    for (; i < end; i++) {
        int   s0 = __ldg(&g_esrc[i]);
        float w0 = __ldg(&g_ew[i]);
        float4 a = __ldg(&Hv[(size_t)s0 * 64 + lane]);
        float4 b = __ldg(&Hv[(size_t)s0 * 64 + lane + 32]);
        lo0.x = fmaf(a.x, w0, lo0.x); lo0.y = fmaf(a.y, w0, lo0.y);
        lo0.z = fmaf(a.z, w0, lo0.z); lo0.w = fmaf(a.w, w0, lo0.w);
        hi0.x = fmaf(b.x, w0, hi0.x); hi0.y = fmaf(b.y, w0, hi0.y);
        hi0.z = fmaf(b.z, w0, hi0.z); hi0.w = fmaf(b.w, w0, hi0.w);
    }
    lo0.x += lo1.x; lo0.y += lo1.y; lo0.z += lo1.z; lo0.w += lo1.w;
    hi0.x += hi1.x; hi0.y += hi1.y; hi0.z += hi1.z; hi0.w += hi1.w;

    float nd = g_ndst[node];
    float4 bl = __ldg(&((const float4*)bias)[lane]);
    float4 bh = __ldg(&((const float4*)bias)[lane + 32]);
    float4 rl, rh;
    rl.x = fmaxf(lo0.x * nd + bl.x, 0.f); rl.y = fmaxf(lo0.y * nd + bl.y, 0.f);
    rl.z = fmaxf(lo0.z * nd + bl.z, 0.f); rl.w = fmaxf(lo0.w * nd + bl.w, 0.f);
    rh.x = fmaxf(hi0.x * nd + bh.x, 0.f); rh.y = fmaxf(hi0.y * nd + bh.y, 0.f);
    rh.z = fmaxf(hi0.z * nd + bh.z, 0.f); rh.w = fmaxf(hi0.w * nd + bh.w, 0.f);
    ((float4*)out)[(size_t)node * 64 + lane]      = rl;
    ((float4*)out)[(size_t)node * 64 + lane + 32] = rh;
}

// ---------------- agg F=64: 16 threads/node, 4-way unroll ------------------
__global__ void k_agg64(const float* __restrict__ H, const float* __restrict__ bias,
                        float* __restrict__ out, int N) {
    int node = blockIdx.x * 16 + (threadIdx.x >> 4);
    int lane = threadIdx.x & 15;
    if (node >= N) return;

    int beg = g_row_start[node];
    int end = g_row_start[node + 1];

    const float4* Hv = (const float4*)H;
    float4 a0 = {0,0,0,0}, a1 = {0,0,0,0}, a2 = {0,0,0,0}, a3 = {0,0,0,0};

    int i = beg;
    for (; i + 3 < end; i += 4) {
        int s0 = __ldg(&g_esrc[i]),     s1 = __ldg(&g_esrc[i + 1]);
        int s2 = __ldg(&g_esrc[i + 2]), s3 = __ldg(&g_esrc[i + 3]);
        float w0 = __ldg(&g_ew[i]),     w1 = __ldg(&g_ew[i + 1]);
        float w2 = __ldg(&g_ew[i + 2]), w3 = __ldg(&g_ew[i + 3]);
        float4 v0 = __ldg(&Hv[(size_t)s0 * 16 + lane]);
        float4 v1 = __ldg(&Hv[(size_t)s1 * 16 + lane]);
        float4 v2 = __ldg(&Hv[(size_t)s2 * 16 + lane]);
        float4 v3 = __ldg(&Hv[(size_t)s3 * 16 + lane]);
        a0.x = fmaf(v0.x, w0, a0.x); a0.y = fmaf(v0.y, w0, a0.y);
        a0.z = fmaf(v0.z, w0, a0.z); a0.w = fmaf(v0.w, w0, a0.w);
        a1.x = fmaf(v1.x, w1, a1.x); a1.y = fmaf(v1.y, w1, a1.y);
        a1.z = fmaf(v1.z, w1, a1.z); a1.w = fmaf(v1.w, w1, a1.w);
        a2.x = fmaf(v2.x, w2, a2.x); a2.y = fmaf(v2.y, w2, a2.y);
        a2.z = fmaf(v2.z, w2, a2.z); a2.w = fmaf(v2.w, w2, a2.w);
        a3.x = fmaf(v3.x, w3, a3.x); a3.y = fmaf(v3.y, w3, a3.y);
        a3.z = fmaf(v3.z, w3, a3.z); a3.w = fmaf(v3.w, w3, a3.w);
    }
    for (; i < end; i++) {
        int s0 = __ldg(&g_esrc[i]);
        float w0 = __ldg(&g_ew[i]);
        float4 v0 = __ldg(&Hv[(size_t)s0 * 16 + lane]);
        a0.x = fmaf(v0.x, w0, a0.x); a0.y = fmaf(v0.y, w0, a0.y);
        a0.z = fmaf(v0.z, w0, a0.z); a0.w = fmaf(v0.w, w0, a0.w);
    }
    a0.x += a1.x + a2.x + a3.x; a0.y += a1.y + a2.y + a3.y;
    a0.z += a1.z + a2.z + a3.z; a0.w += a1.w + a2.w + a3.w;

    float nd = g_ndst[node];
    float4 b = __ldg(&((const float4*)bias)[lane]);
    float4 r;
    r.x = a0.x * nd + b.x; r.y = a0.y * nd + b.y;
    r.z = a0.z * nd + b.z; r.w = a0.w * nd + b.w;
    ((float4*)out)[(size_t)node * 16 + lane] = r;
}

// ---------------- launch ----------------------------------------------------
extern "C" void kernel_launch(void* const* d_in, const int* in_sizes, int n_in,
                              void* d_out, int out_size) {
    const float* feat = (const float*)d_in[0];
    const int*   src  = (const int*)  d_in[1];
    const int*   dst  = (const int*)  d_in[2];
    const float* W1   = (const float*)d_in[3];
    const float* b1   = (const float*)d_in[4];
    const float* W2   = (const float*)d_in[5];
    const float* b2   = (const float*)d_in[6];
    float* out = (float*)d_out;

    const int N = in_sizes[0] / K1;   // 50000
    const int E = in_sizes[1];        // 800000

    void *p_H1, *p_A1, *p_H2;
    cudaGetSymbolAddress(&p_H1, g_H1);
    cudaGetSymbolAddress(&p_A1, g_A1);
    cudaGetSymbolAddress(&p_H2, g_H2);

    const int T = 256;
    const int nb = (N + SCANB - 1) / SCANB;

    // Launch order places gemm_wmma at kernel index 3 (ncu -s 5 capture slot),
    // while preserving all dependencies:
    //   scan2/scan3 after scan1; fill after scan3 (+norms from scan1);
    //   agg256 after fill AND gemm1.
    k_init <<<(N + T - 1) / T, T>>>(N);                       // 0
    k_deg  <<<(E + T - 1) / T, T>>>(src, dst, E);             // 1
    k_scan1<<<nb, SCANB>>>(N);                                // 2 (+ norms)
    {
        dim3 grid((N + 127) / 128, F1 / 128);                 // 3  <-- profiled
        gemm_wmma<<<grid, 256>>>(feat, W1, (float*)p_H1, N, K1, F1);
    }
    k_scan2<<<1, SCANB>>>(nb);                                // 4
    k_scan3<<<nb, SCANB>>>(N);                                // 5
    k_fill <<<(E + T - 1) / T, T>>>(src, dst, E);             // 6

    // agg1: A1 = relu(ndst * sum_e ew*H1[src] + b1)
    k_agg256<<<(N + 7) / 8, 256>>>((const float*)p_H1, b1, (float*)p_A1, N);

    // GEMM2 (exact fp32 SIMT): H2 = A1 @ W2
    {
        dim3 grid((N + 127) / 128, 1);
        sgemm<128, 64, 16, 8, 4><<<grid, 256>>>((const float*)p_A1, W2, (float*)p_H2, N, F1, F2);
    }

    // agg2 -> d_out
    k_agg64<<<(N + 15) / 16, 256>>>((const float*)p_H2, b2, out, N);
}

// round 16
// speedup vs baseline: 1.2267x; 1.0205x over previous
#include <cuda_runtime.h>
#include <math.h>
#include <stdint.h>
#include <mma.h>

using namespace nvcuda;

#define NMAX   50000
#define NPAD   50048               // ceil(50000/128)*128 for unmasked wmma stores
#define EMAX   800000
#define K1     512
#define F1     256
#define F2     64
#define SCANB  256

// ---------------- scratch (static device globals) --------------------------
__device__ int   g_deg_out[NMAX];
__device__ int   g_deg_in [NMAX];
__device__ int   g_cursor [NMAX];
__device__ int   g_row_start[NMAX + 1];
__device__ int   g_part[SCANB];
__device__ int   g_esrc[EMAX];
__device__ float g_ew  [EMAX];              // nsrc[src[e]] per bucketed edge
__device__ float g_nsrc[NMAX];
__device__ float g_ndst[NMAX];
__device__ float g_H1[(size_t)NPAD * F1];   // padded: wmma stores full tiles
__device__ float g_A1[(size_t)NMAX * F1];
__device__ float g_H2[(size_t)NMAX * F2];

// ---------------- fused init ------------------------------------------------
__global__ void k_init(int n) {
    int i = blockIdx.x * blockDim.x + threadIdx.x;
    if (i < n) { g_deg_out[i] = 0; g_deg_in[i] = 0; g_cursor[i] = 0; }
}

// ---------------- degrees ---------------------------------------------------
__global__ void k_deg(const int* __restrict__ src, const int* __restrict__ dst, int E) {
    int e = blockIdx.x * blockDim.x + threadIdx.x;
    if (e < E) {
        atomicAdd(&g_deg_out[src[e]], 1);
        atomicAdd(&g_deg_in [dst[e]], 1);
    }
}

// ---------------- scan phase 1 (+ fused norm computation) -------------------
__device__ __forceinline__ int warp_incl_scan(int v) {
#pragma unroll
    for (int off = 1; off < 32; off <<= 1) {
        int t = __shfl_up_sync(0xFFFFFFFFu, v, off);
        if ((threadIdx.x & 31) >= off) v += t;
    }
    return v;
}

__global__ void k_scan1(int n) {
    int i = blockIdx.x * SCANB + threadIdx.x;
    int v = 0;
    if (i < n) {
        int o = g_deg_out[i];
        v = g_deg_in[i];
        g_nsrc[i] = (o > 0) ? rsqrtf((float)o) : 1.0f;
        g_ndst[i] = (v > 0) ? rsqrtf((float)v) : 1.0f;
    }
    int s = v;
#pragma unroll
    for (int off = 16; off > 0; off >>= 1) s += __shfl_down_sync(0xFFFFFFFFu, s, off);
    __shared__ int ws[SCANB / 32];
    if ((threadIdx.x & 31) == 0) ws[threadIdx.x >> 5] = s;
    __syncthreads();
    if (threadIdx.x == 0) {
        int t = 0;
#pragma unroll
        for (int w = 0; w < SCANB / 32; w++) t += ws[w];
        g_part[blockIdx.x] = t;
    }
}

__global__ void k_scan2(int nb) {
    int v = (threadIdx.x < nb) ? g_part[threadIdx.x] : 0;
    int s = warp_incl_scan(v);
    __shared__ int ws[SCANB / 32];
    if ((threadIdx.x & 31) == 31) ws[threadIdx.x >> 5] = s;
    __syncthreads();
    if (threadIdx.x < 32) {
        int w = (threadIdx.x < SCANB / 32) ? ws[threadIdx.x] : 0;
        int sw = warp_incl_scan(w);
        if (threadIdx.x < SCANB / 32) ws[threadIdx.x] = sw;
    }
    __syncthreads();
    int incl = s + ((threadIdx.x >= 32) ? ws[(threadIdx.x >> 5) - 1] : 0);
    if (threadIdx.x < nb) g_part[threadIdx.x] = incl - v;
}

__global__ void k_scan3(int n) {
    int i = blockIdx.x * SCANB + threadIdx.x;
    int v = (i < n) ? g_deg_in[i] : 0;
    int s = warp_incl_scan(v);
    __shared__ int ws[SCANB / 32];
    if ((threadIdx.x & 31) == 31) ws[threadIdx.x >> 5] = s;
    __syncthreads();
    if (threadIdx.x < 32) {
        int w = (threadIdx.x < SCANB / 32) ? ws[threadIdx.x] : 0;
        int sw = warp_incl_scan(w);
        if (threadIdx.x < SCANB / 32) ws[threadIdx.x] = sw;
    }
    __syncthreads();
    int incl = s + ((threadIdx.x >= 32) ? ws[(threadIdx.x >> 5) - 1] : 0);
    int off = g_part[blockIdx.x];
    if (i < n) g_row_start[i] = off + incl - v;
    if (i == n - 1) g_row_start[n] = off + incl;
}

// ---------------- bucket edges by dst --------------------------------------
__global__ void k_fill(const int* __restrict__ src, const int* __restrict__ dst, int E) {
    int e = blockIdx.x * blockDim.x + threadIdx.x;
    if (e < E) {
        int s = src[e];
        int d = dst[e];
        int pos = g_row_start[d] + atomicAdd(&g_cursor[d], 1);
        g_esrc[pos] = s;
        g_ew [pos] = g_nsrc[s];
    }
}

// ---------------- cp.async helpers -----------------------------------------
__device__ __forceinline__ void cp_async16(uint32_t dst, const void* src, bool valid) {
    int sz = valid ? 16 : 0;
    asm volatile("cp.async.cg.shared.global [%0], [%1], 16, %2;"
                 :: "r"(dst), "l"(src), "r"(sz));
}
#define CP_COMMIT()  asm volatile("cp.async.commit_group;")
#define CP_WAIT(n)   asm volatile("cp.async.wait_group %0;" :: "n"(n))

// ---------------- TF32 wmma GEMM1 (cp.async 3-stage):  C = A @ B -----------
// fp32 loaded raw into smem; HMMA truncates to tf32 (RZ). C rows padded.
__global__ void __launch_bounds__(256) gemm_wmma(
    const float* __restrict__ A, const float* __restrict__ B,
    float* __restrict__ C, int M, int K, int N) {
    constexpr int BM = 128, BN = 128, BK = 16;
    constexpr int AST = BK + 4;         // 20 floats/row, 80B (16B-aligned)
    constexpr int BST = BN + 4;         // 132 floats/row, 528B (16B-aligned)
    constexpr int STG = 3;
    constexpr int ASZ = BM * AST;       // floats per A stage
    constexpr int BSZ = BK * BST;       // floats per B stage

    extern __shared__ float smem[];
    float* As = smem;                   // [STG][ASZ]
    float* Bs = smem + STG * ASZ;       // [STG][BSZ]

    const int tid = threadIdx.x;
    const int wid = tid >> 5;
    const int wm  = (wid & 1) * 64;
    const int wn  = (wid >> 1) * 32;
    const int bm  = blockIdx.x * BM;
    const int bn  = blockIdx.y * BN;

    const uint32_t smem_base = (uint32_t)__cvta_generic_to_shared(smem);

    auto issueA = [&](int st, int k0) {
#pragma unroll
        for (int u = 0; u < 2; u++) {
            int idx = tid + u * 256;
            int m   = idx >> 2;
            int kq  = idx & 3;
            int gm  = bm + m;
            uint32_t dst = smem_base + (uint32_t)((st * ASZ + m * AST + kq * 4) * 4);
            cp_async16(dst, A + (size_t)gm * K + k0 + kq * 4, gm < M);
        }
    };
    auto issueB = [&](int st, int k0) {
#pragma unroll
        for (int u = 0; u < 2; u++) {
            int idx = tid + u * 256;
            int k   = idx >> 5;
            int n4  = idx & 31;
            uint32_t dst = smem_base + (uint32_t)((STG * ASZ + st * BSZ + k * BST + n4 * 4) * 4);
            cp_async16(dst, B + (size_t)(k0 + k) * N + bn + n4 * 4, true);
        }
    };

    wmma::fragment<wmma::accumulator, 16, 16, 8, float> fc[4][2];
#pragma unroll
    for (int i = 0; i < 4; i++)
#pragma unroll
        for (int j = 0; j < 2; j++) wmma::fill_fragment(fc[i][j], 0.0f);

    const int nt = K / BK;              // 32

    // prologue: stages 0,1 in flight
    issueA(0, 0); issueB(0, 0); CP_COMMIT();
    issueA(1, BK); issueB(1, BK); CP_COMMIT();

    for (int t = 0; t < nt; t++) {
        CP_WAIT(1);                     // stage t complete (≤1 group pending)
        __syncthreads();

        int st = t % STG;
        const float* Ast = As + st * ASZ;
        const float* Bst = Bs + st * BSZ;

#pragma unroll
        for (int ks = 0; ks < BK; ks += 8) {
            wmma::fragment<wmma::matrix_a, 16, 16, 8, wmma::precision::tf32, wmma::row_major> fa[4];
            wmma::fragment<wmma::matrix_b, 16, 16, 8, wmma::precision::tf32, wmma::row_major> fb[2];
#pragma unroll
            for (int i = 0; i < 4; i++)
                wmma::load_matrix_sync(fa[i], Ast + (wm + i * 16) * AST + ks, AST);
#pragma unroll
            for (int j = 0; j < 2; j++)
                wmma::load_matrix_sync(fb[j], Bst + ks * BST + wn + j * 16, BST);
#pragma unroll
            for (int i = 0; i < 4; i++)
#pragma unroll
                for (int j = 0; j < 2; j++)
                    wmma::mma_sync(fc[i][j], fa[i], fb[j], fc[i][j]);
        }

        __syncthreads();                // stage st free for reuse
        if (t + 2 < nt) {
            int sn = (t + 2) % STG;
            issueA(sn, (t + 2) * BK); issueB(sn, (t + 2) * BK); CP_COMMIT();
        } else {
            CP_COMMIT();                // keep group count in sync for CP_WAIT
        }
    }

#pragma unroll
    for (int i = 0; i < 4; i++)
#pragma unroll
        for (int j = 0; j < 2; j++)
            wmma::store_matrix_sync(
                C + (size_t)(bm + wm + i * 16) * N + bn + wn + j * 16,
                fc[i][j], N, wmma::mem_row_major);
}

// ---------------- fp32 SIMT SGEMM (GEMM2, exact) ---------------------------
template<int BM, int BN, int BK, int TM, int TN>
__global__ void sgemm(const float* __restrict__ A, const float* __restrict__ B,
                      float* __restrict__ C, int M, int K, int N) {
    constexpr int NT  = (BM / TM) * (BN / TN);
    constexpr int ASS = BM + 4;
    __shared__ float As[BK][ASS];
    __shared__ float Bs[BK][BN];

    const int tid  = threadIdx.x;
    const int bm   = blockIdx.x * BM;
    const int bn   = blockIdx.y * BN;
    const int tcol = tid % (BN / TN);
    const int trow = tid / (BN / TN);

    float acc[TM][TN];
#pragma unroll
    for (int i = 0; i < TM; i++)
#pragma unroll
        for (int j = 0; j < TN; j++) acc[i][j] = 0.0f;

    constexpr int AF4 = BM * BK / 4;
    constexpr int BF4 = BK * BN / 4;

    for (int k0 = 0; k0 < K; k0 += BK) {
#pragma unroll
        for (int idx = tid; idx < AF4; idx += NT) {
            int m  = idx / (BK / 4);
            int kk = (idx % (BK / 4)) * 4;
            int gm = bm + m;
            float4 v = make_float4(0.f, 0.f, 0.f, 0.f);
            if (gm < M) v = *(const float4*)(A + (size_t)gm * K + k0 + kk);
            As[kk + 0][m] = v.x; As[kk + 1][m] = v.y;
            As[kk + 2][m] = v.z; As[kk + 3][m] = v.w;
        }
#pragma unroll
        for (int idx = tid; idx < BF4; idx += NT) {
            int k  = idx / (BN / 4);
            int n4 = idx % (BN / 4);
            *(float4*)&Bs[k][n4 * 4] =
                *(const float4*)(B + (size_t)(k0 + k) * N + bn + n4 * 4);
        }
        __syncthreads();

#pragma unroll
        for (int k = 0; k < BK; k++) {
            float ra[TM], rb[TN];
#pragma unroll
            for (int i = 0; i < TM; i += 4) {
                float4 t = *(const float4*)&As[k][trow * TM + i];
                ra[i] = t.x; ra[i + 1] = t.y; ra[i + 2] = t.z; ra[i + 3] = t.w;
            }
#pragma unroll
            for (int j = 0; j < TN; j += 4) {
                float4 t = *(const float4*)&Bs[k][tcol * TN + j];
                rb[j] = t.x; rb[j + 1] = t.y; rb[j + 2] = t.z; rb[j + 3] = t.w;
            }
#pragma unroll
            for (int i = 0; i < TM; i++)
#pragma unroll
                for (int j = 0; j < TN; j++)
                    acc[i][j] = fmaf(ra[i], rb[j], acc[i][j]);
        }
        __syncthreads();
    }

#pragma unroll
    for (int i = 0; i < TM; i++) {
        int gm = bm + trow * TM + i;
        if (gm < M) {
#pragma unroll
            for (int j = 0; j < TN; j += 4) {
                float4 t = make_float4(acc[i][j], acc[i][j + 1], acc[i][j + 2], acc[i][j + 3]);
                *(float4*)(C + (size_t)gm * N + bn + tcol * TN + j) = t;
            }
        }
    }
}

// ---------------- agg F=256: one warp/node, 4-edge unroll ------------------
__global__ void k_agg256(const float* __restrict__ H, const float* __restrict__ bias,
                         float* __restrict__ out, int N) {
    int node = blockIdx.x * 8 + (threadIdx.x >> 5);
    int lane = threadIdx.x & 31;
    if (node >= N) return;

    int beg = g_row_start[node];
    int end = g_row_start[node + 1];

    const float4* Hv = (const float4*)H;   // 64 float4 per row
    float4 lo0 = {0,0,0,0}, hi0 = {0,0,0,0};
    float4 lo1 = {0,0,0,0}, hi1 = {0,0,0,0};

    int i = beg;
    for (; i + 3 < end; i += 4) {
        int   s0 = __ldg(&g_esrc[i]),     s1 = __ldg(&g_esrc[i + 1]);
        int   s2 = __ldg(&g_esrc[i + 2]), s3 = __ldg(&g_esrc[i + 3]);
        float w0 = __ldg(&g_ew[i]),       w1 = __ldg(&g_ew[i + 1]);
        float w2 = __ldg(&g_ew[i + 2]),   w3 = __ldg(&g_ew[i + 3]);
        float4 a = __ldg(&Hv[(size_t)s0 * 64 + lane]);
        float4 b = __ldg(&Hv[(size_t)s0 * 64 + lane + 32]);
        float4 c = __ldg(&Hv[(size_t)s1 * 64 + lane]);
        float4 d = __ldg(&Hv[(size_t)s1 * 64 + lane + 32]);
        float4 e = __ldg(&Hv[(size_t)s2 * 64 + lane]);
        float4 f = __ldg(&Hv[(size_t)s2 * 64 + lane + 32]);
        float4 g = __ldg(&Hv[(size_t)s3 * 64 + lane]);
        float4 h = __ldg(&Hv[(size_t)s3 * 64 + lane + 32]);
        lo0.x = fmaf(a.x, w0, lo0.x); lo0.y = fmaf(a.y, w0, lo0.y);
        lo0.z = fmaf(a.z, w0, lo0.z); lo0.w = fmaf(a.w, w0, lo0.w);
        hi0.x = fmaf(b.x, w0, hi0.x); hi0.y = fmaf(b.y, w0, hi0.y);
        hi0.z = fmaf(b.z, w0, hi0.z); hi0.w = fmaf(b.w, w0, hi0.w);
        lo1.x = fmaf(c.x, w1, lo1.x); lo1.y = fmaf(c.y, w1, lo1.y);
        lo1.z = fmaf(c.z, w1, lo1.z); lo1.w = fmaf(c.w, w1, lo1.w);
        hi1.x = fmaf(d.x, w1, hi1.x); hi1.y = fmaf(d.y, w1, hi1.y);
        hi1.z = fmaf(d.z, w1, hi1.z); hi1.w = fmaf(d.w, w1, hi1.w);
        lo0.x = fmaf(e.x, w2, lo0.x); lo0.y = fmaf(e.y, w2, lo0.y);
        lo0.z = fmaf(e.z, w2, lo0.z); lo0.w = fmaf(e.w, w2, lo0.w);
        hi0.x = fmaf(f.x, w2, hi0.x); hi0.y = fmaf(f.y, w2, hi0.y);
        hi0.z = fmaf(f.z, w2, hi0.z); hi0.w = fmaf(f.w, w2, hi0.w);
        lo1.x = fmaf(g.x, w3, lo1.x); lo1.y = fmaf(g.y, w3, lo1.y);
        lo1.z = fmaf(g.z, w3, lo1.z); lo1.w = fmaf(g.w, w3, lo1.w);
        hi1.x = fmaf(h.x, w3, hi1.x); hi1.y = fmaf(h.y, w3, hi1.y);
        hi1.z = fmaf(h.z, w3, hi1.z); hi1.w = fmaf(h.w, w3, hi1.w);
    }
    for (; i < end; i++) {
        int   s0 = __ldg(&g_esrc[i]);
        float w0 = __ldg(&g_ew[i]);
        float4 a = __ldg(&Hv[(size_t)s0 * 64 + lane]);
        float4 b = __ldg(&Hv[(size_t)s0 * 64 + lane + 32]);
        lo0.x = fmaf(a.x, w0, lo0.x); lo0.y = fmaf(a.y, w0, lo0.y);
        lo0.z = fmaf(a.z, w0, lo0.z); lo0.w = fmaf(a.w, w0, lo0.w);
        hi0.x = fmaf(b.x, w0, hi0.x); hi0.y = fmaf(b.y, w0, hi0.y);
        hi0.z = fmaf(b.z, w0, hi0.z); hi0.w = fmaf(b.w, w0, hi0.w);
    }
    lo0.x += lo1.x; lo0.y += lo1.y; lo0.z += lo1.z; lo0.w += lo1.w;
    hi0.x += hi1.x; hi0.y += hi1.y; hi0.z += hi1.z; hi0.w += hi1.w;

    float nd = g_ndst[node];
    float4 bl = __ldg(&((const float4*)bias)[lane]);
    float4 bh = __ldg(&((const float4*)bias)[lane + 32]);
    float4 rl, rh;
    rl.x = fmaxf(lo0.x * nd + bl.x, 0.f); rl.y = fmaxf(lo0.y * nd + bl.y, 0.f);
    rl.z = fmaxf(lo0.z * nd + bl.z, 0.f); rl.w = fmaxf(lo0.w * nd + bl.w, 0.f);
    rh.x = fmaxf(hi0.x * nd + bh.x, 0.f); rh.y = fmaxf(hi0.y * nd + bh.y, 0.f);
    rh.z = fmaxf(hi0.z * nd + bh.z, 0.f); rh.w = fmaxf(hi0.w * nd + bh.w, 0.f);
    ((float4*)out)[(size_t)node * 64 + lane]      = rl;
    ((float4*)out)[(size_t)node * 64 + lane + 32] = rh;
}

// ---------------- agg F=64: 16 threads/node, 4-way unroll ------------------
__global__ void k_agg64(const float* __restrict__ H, const float* __restrict__ bias,
                        float* __restrict__ out, int N) {
    int node = blockIdx.x * 16 + (threadIdx.x >> 4);
    int lane = threadIdx.x & 15;
    if (node >= N) return;

    int beg = g_row_start[node];
    int end = g_row_start[node + 1];

    const float4* Hv = (const float4*)H;
    float4 a0 = {0,0,0,0}, a1 = {0,0,0,0}, a2 = {0,0,0,0}, a3 = {0,0,0,0};

    int i = beg;
    for (; i + 3 < end; i += 4) {
        int s0 = __ldg(&g_esrc[i]),     s1 = __ldg(&g_esrc[i + 1]);
        int s2 = __ldg(&g_esrc[i + 2]), s3 = __ldg(&g_esrc[i + 3]);
        float w0 = __ldg(&g_ew[i]),     w1 = __ldg(&g_ew[i + 1]);
        float w2 = __ldg(&g_ew[i + 2]), w3 = __ldg(&g_ew[i + 3]);
        float4 v0 = __ldg(&Hv[(size_t)s0 * 16 + lane]);
        float4 v1 = __ldg(&Hv[(size_t)s1 * 16 + lane]);
        float4 v2 = __ldg(&Hv[(size_t)s2 * 16 + lane]);
        float4 v3 = __ldg(&Hv[(size_t)s3 * 16 + lane]);
        a0.x = fmaf(v0.x, w0, a0.x); a0.y = fmaf(v0.y, w0, a0.y);
        a0.z = fmaf(v0.z, w0, a0.z); a0.w = fmaf(v0.w, w0, a0.w);
        a1.x = fmaf(v1.x, w1, a1.x); a1.y = fmaf(v1.y, w1, a1.y);
        a1.z = fmaf(v1.z, w1, a1.z); a1.w = fmaf(v1.w, w1, a1.w);
        a2.x = fmaf(v2.x, w2, a2.x); a2.y = fmaf(v2.y, w2, a2.y);
        a2.z = fmaf(v2.z, w2, a2.z); a2.w = fmaf(v2.w, w2, a2.w);
        a3.x = fmaf(v3.x, w3, a3.x); a3.y = fmaf(v3.y, w3, a3.y);
        a3.z = fmaf(v3.z, w3, a3.z); a3.w = fmaf(v3.w, w3, a3.w);
    }
    for (; i < end; i++) {
        int s0 = __ldg(&g_esrc[i]);
        float w0 = __ldg(&g_ew[i]);
        float4 v0 = __ldg(&Hv[(size_t)s0 * 16 + lane]);
        a0.x = fmaf(v0.x, w0, a0.x); a0.y = fmaf(v0.y, w0, a0.y);
        a0.z = fmaf(v0.z, w0, a0.z); a0.w = fmaf(v0.w, w0, a0.w);
    }
    a0.x += a1.x + a2.x + a3.x; a0.y += a1.y + a2.y + a3.y;
    a0.z += a1.z + a2.z + a3.z; a0.w += a1.w + a2.w + a3.w;

    float nd = g_ndst[node];
    float4 b = __ldg(&((const float4*)bias)[lane]);
    float4 r;
    r.x = a0.x * nd + b.x; r.y = a0.y * nd + b.y;
    r.z = a0.z * nd + b.z; r.w = a0.w * nd + b.w;
    ((float4*)out)[(size_t)node * 16 + lane] = r;
}

// ---------------- launch ----------------------------------------------------
extern "C" void kernel_launch(void* const* d_in, const int* in_sizes, int n_in,
                              void* d_out, int out_size) {
    const float* feat = (const float*)d_in[0];
    const int*   src  = (const int*)  d_in[1];
    const int*   dst  = (const int*)  d_in[2];
    const float* W1   = (const float*)d_in[3];
    const float* b1   = (const float*)d_in[4];
    const float* W2   = (const float*)d_in[5];
    const float* b2   = (const float*)d_in[6];
    float* out = (float*)d_out;

    const int N = in_sizes[0] / K1;   // 50000
    const int E = in_sizes[1];        // 800000

    void *p_H1, *p_A1, *p_H2;
    cudaGetSymbolAddress(&p_H1, g_H1);
    cudaGetSymbolAddress(&p_A1, g_A1);
    cudaGetSymbolAddress(&p_H2, g_H2);

    const int T = 256;
    const int nb = (N + SCANB - 1) / SCANB;

    // dynamic smem for the 3-stage GEMM1: 3*(128*20 + 16*132)*4 = 56064 B
    const int GEMM1_SMEM = 3 * (128 * 20 + 16 * 132) * 4;
    static bool attr_set = false;
    if (!attr_set) {
        cudaFuncSetAttribute(gemm_wmma, cudaFuncAttributeMaxDynamicSharedMemorySize, GEMM1_SMEM);
        attr_set = true;
    }

    // Launch order keeps gemm_wmma at kernel index 3 (ncu capture slot).
    k_init <<<(N + T - 1) / T, T>>>(N);                       // 0
    k_deg  <<<(E + T - 1) / T, T>>>(src, dst, E);             // 1
    k_scan1<<<nb, SCANB>>>(N);                                // 2 (+ norms)
    {
        dim3 grid((N + 127) / 128, F1 / 128);                 // 3  <-- profiled
        gemm_wmma<<<grid, 256, GEMM1_SMEM>>>(feat, W1, (float*)p_H1, N, K1, F1);
    }
    k_scan2<<<1, SCANB>>>(nb);                                // 4
    k_scan3<<<nb, SCANB>>>(N);                                // 5
    k_fill <<<(E + T - 1) / T, T>>>(src, dst, E);             // 6

    // agg1: A1 = relu(ndst * sum_e ew*H1[src] + b1)
    k_agg256<<<(N + 7) / 8, 256>>>((const float*)p_H1, b1, (float*)p_A1, N);

    // GEMM2 (exact fp32 SIMT): H2 = A1 @ W2
    {
        dim3 grid((N + 127) / 128, 1);
        sgemm<128, 64, 16, 8, 4><<<grid, 256>>>((const float*)p_A1, W2, (float*)p_H2, N, F1, F2);
    }

    // agg2 -> d_out
    k_agg64<<<(N + 15) / 16, 256>>>((const float*)p_H2, b2, out, N);
}